// round 7
// baseline (speedup 1.0000x reference)
#include <cuda_runtime.h>
#include <cuda_bf16.h>
#include <math.h>
#include <stdint.h>

#define BSZ 4
#define SEQ 2048
#define DMODEL 512
#define NH 8
#define HDIM 64
#define KW1 64
#define KW2 64
#define MROWS (BSZ * SEQ)   // 8192

typedef unsigned long long u64;

// ---------------- scratch (device globals; allocation-free) ----------------
__device__ float g_q[(size_t)BSZ * NH * SEQ * HDIM];   // [B,H,L,HD]
__device__ float g_k[(size_t)BSZ * NH * SEQ * HDIM];
__device__ float g_v[(size_t)BSZ * NH * SEQ * HDIM];
__device__ float g_u[(size_t)MROWS * DMODEL];          // [B,L,D]

// split-bf16 operands (hi + lo, K-major rows of 512)
__device__ __nv_bfloat16 gXh[(size_t)MROWS * DMODEL];
__device__ __nv_bfloat16 gXl[(size_t)MROWS * DMODEL];
__device__ __nv_bfloat16 gWh[(size_t)2048 * DMODEL];   // [w_qkv ; w_u]
__device__ __nv_bfloat16 gWl[(size_t)2048 * DMODEL];
__device__ __nv_bfloat16 gOh[(size_t)DMODEL * DMODEL]; // w_out
__device__ __nv_bfloat16 gOl[(size_t)DMODEL * DMODEL];
__device__ __nv_bfloat16 gGh[(size_t)MROWS * DMODEL];  // gated activations
__device__ __nv_bfloat16 gGl[(size_t)MROWS * DMODEL];

// ======================= PTX helpers =======================
__device__ __forceinline__ uint32_t smem_u32(const void* p) {
    uint32_t a;
    asm("{ .reg .u64 t; cvta.to.shared.u64 t, %1; cvt.u32.u64 %0, t; }"
        : "=r"(a) : "l"(p));
    return a;
}
#define CP_ASYNC16(dst, src) \
    asm volatile("cp.async.cg.shared.global [%0], [%1], 16;" :: "r"(dst), "l"(src) : "memory")
#define CP_COMMIT() asm volatile("cp.async.commit_group;" ::: "memory")
#define CP_WAIT(n) asm volatile("cp.async.wait_group %0;" :: "n"(n) : "memory")

__device__ __forceinline__ void ldsm4(uint32_t r[4], uint32_t addr) {
    asm volatile("ldmatrix.sync.aligned.m8n8.x4.shared.b16 {%0,%1,%2,%3}, [%4];"
                 : "=r"(r[0]), "=r"(r[1]), "=r"(r[2]), "=r"(r[3]) : "r"(addr));
}
__device__ __forceinline__ void mma16816(float c[4], const uint32_t a[4],
                                         const uint32_t b[2]) {
    asm volatile(
        "mma.sync.aligned.m16n8k16.row.col.f32.bf16.bf16.f32 "
        "{%0,%1,%2,%3},{%4,%5,%6,%7},{%8,%9},{%0,%1,%2,%3};"
        : "+f"(c[0]), "+f"(c[1]), "+f"(c[2]), "+f"(c[3])
        : "r"(a[0]), "r"(a[1]), "r"(a[2]), "r"(a[3]), "r"(b[0]), "r"(b[1]));
}

// packed fp32x2 (sm_100+): FFMA2 only reachable via PTX
__device__ __forceinline__ u64 f2pack(float x, float y) {
    u64 r; asm("mov.b64 %0, {%1, %2};" : "=l"(r) : "f"(x), "f"(y)); return r;
}
__device__ __forceinline__ float2 f2unpack(u64 v) {
    float2 o; asm("mov.b64 {%0, %1}, %2;" : "=f"(o.x), "=f"(o.y) : "l"(v)); return o;
}
__device__ __forceinline__ u64 ffma2(u64 a, u64 b, u64 c) {
    u64 d; asm("fma.rn.f32x2 %0, %1, %2, %3;" : "=l"(d) : "l"(a), "l"(b), "l"(c));
    return d;
}

// ======================= fused split conversion =======================
// One launch for [x | w_qkv | w_u | w_out] -> (hi, lo) bf16 pairs.
#define SN0 (MROWS * DMODEL)          // 4194304  x
#define SN1 (1536 * DMODEL)           // 786432   w_qkv
#define SN2 (512 * DMODEL)            // 262144   w_u
#define SN3 (512 * DMODEL)            // 262144   w_out
#define SNT (SN0 + SN1 + SN2 + SN3)   // 5505024 = 21504 * 256

__global__ void __launch_bounds__(256)
split_all(const float* __restrict__ x, const float* __restrict__ wqkv,
          const float* __restrict__ wu, const float* __restrict__ wout)
{
    const int i = blockIdx.x * 256 + threadIdx.x;
    const float* src;
    __nv_bfloat16 *h, *l;
    int idx;
    if (i < SN0) {
        src = x; idx = i; h = gXh; l = gXl;
    } else if (i < SN0 + SN1) {
        src = wqkv; idx = i - SN0; h = gWh; l = gWl;
    } else if (i < SN0 + SN1 + SN2) {
        src = wu; idx = i - (SN0 + SN1);
        h = gWh + (size_t)1536 * DMODEL; l = gWl + (size_t)1536 * DMODEL;
    } else {
        src = wout; idx = i - (SN0 + SN1 + SN2); h = gOh; l = gOl;
    }
    const float a = src[idx];
    const __nv_bfloat16 hv = __float2bfloat16(a);
    h[idx] = hv;
    l[idx] = __float2bfloat16(a - __bfloat162float(hv));
}

// ======================= HMMA split-bf16 GEMM =======================
// C[M,N] = (Ah+Al)[M,512] @ (Bh+Bl)[N,512]^T   (hh + lh + hl terms)
// Block tile 128x128, BK=32, 256 thr = 8 warps (2m x 4n), warp tile 64x32.
// smem: 128 rows x 64B, XOR swizzle chunk^((row>>1)&3); 32KB/stage,
// 3-stage ring (96KB) -> still 2 CTAs/SM, single __syncthreads per iter.
#define TILEB 8192                // 128 * 64
#define STAGEB (4 * TILEB)        // Ah, Al, Bh, Bl
#define GSMEM (3 * STAGEB)        // 98304

template <int MODE>
__global__ void __launch_bounds__(256, 2)
gemm_hmma(const __nv_bfloat16* __restrict__ Ah, const __nv_bfloat16* __restrict__ Al,
          const __nv_bfloat16* __restrict__ Bh, const __nv_bfloat16* __restrict__ Bl,
          const float* __restrict__ bias1, const float* __restrict__ bias2,
          float* __restrict__ C, int Ntot)
{
    extern __shared__ char smem[];
    const uint32_t sb = smem_u32(smem);
    const int tid = threadIdx.x, lane = tid & 31, wid = tid >> 5;
    const int wm = wid & 1, wn = wid >> 1;        // 2 x 4 warp grid
    const int m0 = blockIdx.y * 128, n0 = blockIdx.x * 128;

    // loader: 4 op-tiles x 64 threads; thread covers 8 (row,chunk) slots
    const int lt = tid >> 6;
    const int lidx = tid & 63;
    const __nv_bfloat16* lbase;
    {
        const __nv_bfloat16* s0 = Ah + (size_t)m0 * 512;
        const __nv_bfloat16* s1 = Al + (size_t)m0 * 512;
        const __nv_bfloat16* s2 = Bh + (size_t)n0 * 512;
        const __nv_bfloat16* s3 = Bl + (size_t)n0 * 512;
        lbase = (lt == 0) ? s0 : (lt == 1) ? s1 : (lt == 2) ? s2 : s3;
    }
    const int lrow0 = lidx >> 2;          // 0..15 (step 16 per it)
    const int lch = lidx & 3;
    const int lsc = lch ^ ((lrow0 >> 1) & 3);   // swizzled 16B slot
    const uint32_t ldst0 = sb + lt * TILEB + lrow0 * 64 + lsc * 16;
    const __nv_bfloat16* lsrc0 = lbase + (size_t)lrow0 * 512 + lch * 8;

    auto load_stage = [&](int s) {
        const uint32_t d0 = ldst0 + (s % 3) * STAGEB;
        const __nv_bfloat16* g0 = lsrc0 + s * 32;
#pragma unroll
        for (int it = 0; it < 8; it++)
            CP_ASYNC16(d0 + it * 1024, g0 + (size_t)it * (16 * 512));
    };

    float acc[4][4][4];
#pragma unroll
    for (int a = 0; a < 4; a++)
#pragma unroll
        for (int b = 0; b < 4; b++)
#pragma unroll
            for (int c = 0; c < 4; c++) acc[a][b][c] = 0.f;

    // frag addressing (lane constants; im*16 rows keep (row>>1)&3 invariant)
    const int arow = wm * 64 + (lane & 15);
    const int asub = lane >> 4;
    const int aswz = (arow >> 1) & 3;
    const uint32_t abase = arow * 64;
    const int brow = wn * 32 + (lane & 7) + ((lane >> 4) << 3);
    const int bsub = (lane >> 3) & 1;
    const int bswz = (brow >> 1) & 3;
    const uint32_t bbase = brow * 64;

    load_stage(0); CP_COMMIT();
    load_stage(1); CP_COMMIT();

#pragma unroll 1
    for (int s = 0; s < 16; s++) {
        if (s < 15) CP_WAIT(1); else CP_WAIT(0);
        __syncthreads();
        if (s + 2 < 16) { load_stage(s + 2); CP_COMMIT(); }
        const uint32_t st = sb + (s % 3) * STAGEB;
#pragma unroll
        for (int kp = 0; kp < 2; kp++) {
            const uint32_t aoff = abase + (((kp * 2 + asub) ^ aswz) * 16);
            const uint32_t boff = bbase + (((kp * 2 + bsub) ^ bswz) * 16);
            uint32_t ah[4][4], al[4][4], bb[4][2];
#pragma unroll
            for (int im = 0; im < 4; im++)
                ldsm4(ah[im], st + 0 * TILEB + aoff + im * 1024);
#pragma unroll
            for (int jn = 0; jn < 2; jn++) {
                uint32_t r[4];
                ldsm4(r, st + 2 * TILEB + boff + jn * 1024);
                bb[jn * 2][0] = r[0]; bb[jn * 2][1] = r[1];
                bb[jn * 2 + 1][0] = r[2]; bb[jn * 2 + 1][1] = r[3];
            }
#pragma unroll
            for (int im = 0; im < 4; im++)
#pragma unroll
                for (int in = 0; in < 4; in++) mma16816(acc[im][in], ah[im], bb[in]);
#pragma unroll
            for (int im = 0; im < 4; im++)
                ldsm4(al[im], st + 1 * TILEB + aoff + im * 1024);
#pragma unroll
            for (int im = 0; im < 4; im++)
#pragma unroll
                for (int in = 0; in < 4; in++) mma16816(acc[im][in], al[im], bb[in]);
#pragma unroll
            for (int jn = 0; jn < 2; jn++) {
                uint32_t r[4];
                ldsm4(r, st + 3 * TILEB + boff + jn * 1024);
                bb[jn * 2][0] = r[0]; bb[jn * 2][1] = r[1];
                bb[jn * 2 + 1][0] = r[2]; bb[jn * 2 + 1][1] = r[3];
            }
#pragma unroll
            for (int im = 0; im < 4; im++)
#pragma unroll
                for (int in = 0; in < 4; in++) mma16816(acc[im][in], ah[im], bb[in]);
        }
    }

    // ---------------- epilogue (from registers) ----------------
    const int r0 = m0 + wm * 64 + (lane >> 2);
    const int cb = n0 + wn * 32;
#pragma unroll
    for (int im = 0; im < 4; im++) {
#pragma unroll
        for (int in = 0; in < 4; in++) {
            const int col = cb + in * 8 + (lane & 3) * 2;
            if (MODE == 0) {
                const int nb = cb + in * 8;       // frag-uniform segment
                const bool isu = (nb >= 1536);
                float bx, by;
                float* dst = nullptr;
                int h = 0;
                if (!isu) {
                    const int sg = nb >> 9;
                    h = (nb >> 6) & 7;
                    dst = (sg == 0) ? g_q : (sg == 1) ? g_k : g_v;
                    const float2 bv = *(const float2*)&bias1[col];
                    bx = bv.x; by = bv.y;
                } else {
                    const float2 bv = *(const float2*)&bias2[col - 1536];
                    bx = bv.x; by = bv.y;
                }
#pragma unroll
                for (int hf = 0; hf < 2; hf++) {
                    const int row = r0 + im * 16 + hf * 8;
                    float2 v;
                    v.x = acc[im][in][hf * 2] + bx;
                    v.y = acc[im][in][hf * 2 + 1] + by;
                    if (!isu) {
                        const int bb2 = row >> 11, l = row & (SEQ - 1);
                        *(float2*)&dst[(((size_t)(bb2 * NH + h)) * SEQ + l) * HDIM +
                                       (col & 63)] = v;
                    } else {
                        *(float2*)&g_u[(size_t)row * DMODEL + (col - 1536)] = v;
                    }
                }
            } else {
                const float2 bv = *(const float2*)&bias1[col];
#pragma unroll
                for (int hf = 0; hf < 2; hf++) {
                    const int row = r0 + im * 16 + hf * 8;
                    float2 v;
                    v.x = acc[im][in][hf * 2] + bv.x;
                    v.y = acc[im][in][hf * 2 + 1] + bv.y;
                    *(float2*)&C[(size_t)row * Ntot + col] = v;
                }
            }
        }
    }
}

// ---------------- sparse semi-local attention + SiLU gate ----------------
// One warp per 4 consecutive queries. QK dots and PV accumulate use packed
// fma.rn.f32x2; probs stored pre-packed (u64) in smem for PV broadcast.
#define NTMAX 160
__global__ void __launch_bounds__(256)
attn_kernel()
{
    __shared__ u64 sp[8][4][NTMAX];
    const int wid = threadIdx.x >> 5, lane = threadIdx.x & 31;
    const int gw = blockIdx.x * 8 + wid;          // 0..16383
    const int qb = (gw << 2) & (SEQ - 1);
    const int bh = (gw << 2) >> 11;

    // union key-range for queries qb..qb+3
    int p_hi = 0, bhi = 0;
#pragma unroll
    for (int qq = 0; qq < 4; qq++) {
        const int ii = qb + qq;
        p_hi = max(p_hi, min(min(KW2, SEQ - ii), ii));
        bhi  = max(bhi, min(ii, SEQ - ii));
    }
    const int blo = max(SEQ - KW1 - (qb + 3), p_hi + 1);
    const int n1 = p_hi + 1;
    const int n2 = max(0, bhi - blo + 1);
    const int nt = n1 + n2;

    const float* kbase = g_k + (size_t)bh * SEQ * HDIM;
    const float* vbase = g_v + (size_t)bh * SEQ * HDIM;

    const int c = lane & 7;             // 16B chunk within row (c and c+8)
    const int g = lane >> 3;            // key sub-index within 4-key group

    u64 qp[4][4];                       // 4 queries x 4 packed f32x2 pairs
#pragma unroll
    for (int qq = 0; qq < 4; qq++) {
        const float* qrow = g_q + ((size_t)bh * SEQ + qb + qq) * HDIM;
        const ulonglong2 a = *(const ulonglong2*)(qrow + c * 4);
        const ulonglong2 b = *(const ulonglong2*)(qrow + 32 + c * 4);
        qp[qq][0] = a.x; qp[qq][1] = a.y; qp[qq][2] = b.x; qp[qq][3] = b.y;
    }

    // ---- QK^T over union slots (packed dots) ----
    const int ngroups = (nt + 3) >> 2;
    for (int it = 0; it < ngroups; it++) {
        const int t = it * 4 + g;
        const bool valid = t < nt;
        int j = (t < n1) ? t : blo + (t - n1);
        j = valid ? j : 0;
        const float* krow = kbase + (size_t)j * HDIM;
        const ulonglong2 ka = *(const ulonglong2*)(krow + c * 4);
        const ulonglong2 kc = *(const ulonglong2*)(krow + 32 + c * 4);
        float p[4];
#pragma unroll
        for (int qq = 0; qq < 4; qq++) {
            u64 acc = ffma2(qp[qq][0], ka.x, 0ull);
            acc = ffma2(qp[qq][1], ka.y, acc);
            acc = ffma2(qp[qq][2], kc.x, acc);
            acc = ffma2(qp[qq][3], kc.y, acc);
            const float2 h = f2unpack(acc);
            p[qq] = h.x + h.y;
        }
#pragma unroll
        for (int off = 4; off; off >>= 1) {
            p[0] += __shfl_xor_sync(0xffffffffu, p[0], off);
            p[1] += __shfl_xor_sync(0xffffffffu, p[1], off);
            p[2] += __shfl_xor_sync(0xffffffffu, p[2], off);
            p[3] += __shfl_xor_sync(0xffffffffu, p[3], off);
        }
        if (valid && c == 0) {
#pragma unroll
            for (int qq = 0; qq < 4; qq++) {
                const float sc = p[qq] * 0.125f;
                sp[wid][qq][t] = f2pack(sc, sc);
            }
        }
    }
    __syncwarp();

    // ---- per-query masked softmax (probs written back packed) ----
    float inv_denom[4];
#pragma unroll
    for (int qq = 0; qq < 4; qq++) {
        const int ii = qb + qq;
        float scv[5];
        float m = -INFINITY;
#pragma unroll
        for (int s = 0; s < 5; s++) {
            const int t = lane + 32 * s;
            float v = -INFINITY;
            if (t < nt) {
                const int j = (t < n1) ? t : blo + (t - n1);
                const bool ok = (j <= ii) &&
                    (((ii + j >= SEQ - KW1) && (ii + j <= SEQ)) ||
                     ((j <= KW2) && (j <= SEQ - ii)));
                v = ok ? f2unpack(sp[wid][qq][t]).x : -INFINITY;
            }
            scv[s] = v;
            m = fmaxf(m, v);
        }
#pragma unroll
        for (int off = 16; off; off >>= 1)
            m = fmaxf(m, __shfl_xor_sync(0xffffffffu, m, off));
        float lsum = 0.f;
#pragma unroll
        for (int s = 0; s < 5; s++) {
            const int t = lane + 32 * s;
            if (t < nt) {
                const float e = __expf(scv[s] - m);
                lsum += e;
                sp[wid][qq][t] = f2pack(e, e);
            }
        }
#pragma unroll
        for (int off = 16; off; off >>= 1)
            lsum += __shfl_xor_sync(0xffffffffu, lsum, off);
        inv_denom[qq] = 1.f / lsum;
    }
    __syncwarp();

    // ---- P @ V (packed accumulate; probs via LDS.64 broadcast) ----
    u64 ov[4] = {0ull, 0ull, 0ull, 0ull};
    const float* vlane = vbase + 2 * lane;
#pragma unroll 2
    for (int t = 0; t < nt; t++) {
        const int j = (t < n1) ? t : blo + (t - n1);
        const u64 vv = *(const u64*)(vlane + (size_t)j * HDIM);
#pragma unroll
        for (int qq = 0; qq < 4; qq++)
            ov[qq] = ffma2(sp[wid][qq][t], vv, ov[qq]);
    }

    // ---- SiLU gate + fused bf16 split write ----
    const int b = bh >> 3;
    const int h = bh & 7;
#pragma unroll
    for (int qq = 0; qq < 4; qq++) {
        const float2 o = f2unpack(ov[qq]);
        const float a0 = o.x * inv_denom[qq];
        const float a1 = o.y * inv_denom[qq];
        const size_t uidx =
            ((size_t)(b * SEQ + qb + qq)) * DMODEL + h * HDIM + 2 * lane;
        const float2 uu = *(const float2*)(g_u + uidx);
        const float gx = (a0 / (1.f + __expf(-a0))) * uu.x;
        const float gy = (a1 / (1.f + __expf(-a1))) * uu.y;
        __nv_bfloat162 hv, lv;
        hv.x = __float2bfloat16(gx);
        hv.y = __float2bfloat16(gy);
        lv.x = __float2bfloat16(gx - __bfloat162float(hv.x));
        lv.y = __float2bfloat16(gy - __bfloat162float(hv.y));
        *(__nv_bfloat162*)&gGh[uidx] = hv;
        *(__nv_bfloat162*)&gGl[uidx] = lv;
    }
}

// ---------------- launch ----------------
extern "C" void kernel_launch(void* const* d_in, const int* in_sizes, int n_in,
                              void* d_out, int out_size)
{
    const float* x     = (const float*)d_in[0];
    const float* w_qkv = (const float*)d_in[1];
    const float* b_qkv = (const float*)d_in[2];
    const float* w_u   = (const float*)d_in[3];
    const float* b_u   = (const float*)d_in[4];
    const float* w_out = (const float*)d_in[5];
    const float* b_out = (const float*)d_in[6];
    float* out = (float*)d_out;

    void *pXh, *pXl, *pWh, *pWl, *pOh, *pOl, *pGh, *pGl;
    cudaGetSymbolAddress(&pXh, gXh); cudaGetSymbolAddress(&pXl, gXl);
    cudaGetSymbolAddress(&pWh, gWh); cudaGetSymbolAddress(&pWl, gWl);
    cudaGetSymbolAddress(&pOh, gOh); cudaGetSymbolAddress(&pOl, gOl);
    cudaGetSymbolAddress(&pGh, gGh); cudaGetSymbolAddress(&pGl, gGl);

    cudaFuncSetAttribute(gemm_hmma<0>, cudaFuncAttributeMaxDynamicSharedMemorySize, GSMEM);
    cudaFuncSetAttribute(gemm_hmma<1>, cudaFuncAttributeMaxDynamicSharedMemorySize, GSMEM);

    // fused split conversions (x + all weights), one launch
    split_all<<<SNT / 256, 256>>>(x, w_qkv, w_u, w_out);

    // fused QKV+U projection: [8192,512] @ [2048,512]^T on HMMA
    {
        dim3 grid(2048 / 128, MROWS / 128);
        gemm_hmma<0><<<grid, 256, GSMEM>>>(
            (const __nv_bfloat16*)pXh, (const __nv_bfloat16*)pXl,
            (const __nv_bfloat16*)pWh, (const __nv_bfloat16*)pWl,
            b_qkv, b_u, nullptr, 2048);
    }

    // sparse attention + SiLU*u gate + fused g-split (4 queries/warp)
    {
        const int warps = BSZ * NH * SEQ / 4;      // 16384
        attn_kernel<<<warps / 8, 256>>>();
    }

    // output projection: [8192,512] @ [512,512]^T on HMMA
    {
        dim3 grid(DMODEL / 128, MROWS / 128);
        gemm_hmma<1><<<grid, 256, GSMEM>>>(
            (const __nv_bfloat16*)pGh, (const __nv_bfloat16*)pGl,
            (const __nv_bfloat16*)pOh, (const __nv_bfloat16*)pOl,
            b_out, nullptr, out, DMODEL);
    }
}